// round 1
// baseline (speedup 1.0000x reference)
#include <cuda_runtime.h>
#include <math_constants.h>
#include <math.h>

#define Bsz 2
#define Nn 1024
#define N1 1025
#define Dm 128
#define Hh 8
#define Dk 16
#define Dff 512
#define NBk 32
#define KNN 10
#define AW 33          // 33 x 32-bit words cover 1025 mask bits per row
#define EPSf 1e-5f
#define SCALEf 0.25f   // 1/sqrt(16)

// ------------------------- persistent device scratch -------------------------
__device__ float    d_HG [Bsz*N1*Dm];     // state: rows 0..1023 = h, row 1024 = g
__device__ float    d_POOL[Bsz*Dm];
__device__ float    d_SQ [Bsz*Nn];
__device__ float    d_D2 [(size_t)Bsz*Nn*Nn];
__device__ unsigned d_ADJ[Bsz*N1*AW];
__device__ float    d_Q  [Bsz*N1*Dm];
__device__ float    d_Kb [Bsz*N1*Dm];
__device__ float    d_Vb [Bsz*N1*Dm];
__device__ float    d_CTX[Bsz*N1*Dm];
__device__ float    d_QE [Bsz*N1*Hh*NBk];
__device__ float    d_Y  [Bsz*N1*Dm];
__device__ float    d_T1 [Bsz*N1*Dff];
__device__ float    d_T2 [Bsz*N1*Dm];
__device__ float    d_X  [Bsz*Nn*Dm];

// ------------------------- input embedding + state init ----------------------
__global__ void k_input(const float* __restrict__ coords, const float* __restrict__ inW,
                        const float* __restrict__ inb, const float* __restrict__ gnode)
{
    int gid = blockIdx.x*blockDim.x + threadIdx.x;
    if (gid < Bsz*Dm) d_POOL[gid] = 0.f;
    if (gid >= Bsz*N1*Dm) return;
    int d = gid % Dm;
    int n = (gid / Dm) % N1;
    int b = gid / (Dm*N1);
    float v;
    if (n < Nn) {
        float x = coords[(b*Nn+n)*2+0];
        float y = coords[(b*Nn+n)*2+1];
        v = x*inW[d*2+0] + y*inW[d*2+1] + inb[d];
    } else {
        v = gnode[d];
    }
    d_HG[gid] = v;
}

// ------------------------- column mean of h (feeds g and pool) --------------
__global__ void k_colmean(int flags)   // bit0: g += mean, bit1: pool += mean
{
    __shared__ float red[8][Dm];
    int b = blockIdx.x;
    int d = threadIdx.x & 127;
    int g = threadIdx.x >> 7;          // 0..7
    const float* base = d_HG + (size_t)b*N1*Dm;
    float s = 0.f;
    for (int n = g; n < Nn; n += 8) s += base[n*Dm + d];
    red[g][d] = s;
    __syncthreads();
    if (g == 0) {
        float t = 0.f;
        #pragma unroll
        for (int i = 0; i < 8; i++) t += red[i][d];
        float m = t * (1.f/Nn);
        if (flags & 1) d_HG[(size_t)b*N1*Dm + Nn*Dm + d] += m;
        if (flags & 2) d_POOL[b*Dm + d] += m;
    }
}

// ------------------------- adjacency base pattern ----------------------------
__global__ void k_init_adj()
{
    int row = blockIdx.x;              // 0 .. Bsz*N1-1
    int i   = row % N1;
    int w   = threadIdx.x;
    if (w >= AW) return;
    unsigned bits = 0u;
    #pragma unroll 4
    for (int t = 0; t < 32; t++) {
        int m = w*32 + t;
        if (m > Nn) break;
        bool on;
        if (i == Nn || m == Nn || i == m || i == 0 || m == 0) on = true;
        else {
            int di = i - m; if (di < 0) di = -di;
            on = ((i >> 7) == (m >> 7)) && (di <= 11);   // hier: same 128-block, stride 11
        }
        if (on) bits |= 1u << t;
    }
    d_ADJ[row*AW + w] = bits;
}

// ------------------------- squared norms ------------------------------------
__global__ void k_sqnorm()
{
    int warp = (blockIdx.x*blockDim.x + threadIdx.x) >> 5;
    int lane = threadIdx.x & 31;
    if (warp >= Bsz*Nn) return;
    int b = warp >> 10, i = warp & 1023;
    const float* p = d_HG + ((size_t)b*N1 + i)*Dm;
    float s = 0.f;
    #pragma unroll
    for (int t = 0; t < 4; t++) { float v = p[lane + t*32]; s += v*v; }
    #pragma unroll
    for (int o = 16; o; o >>= 1) s += __shfl_xor_sync(0xffffffffu, s, o);
    if (!lane) d_SQ[warp] = s;
}

// ------------------------- D2 matrix (tiled) ---------------------------------
__global__ void k_d2()
{
    __shared__ float As[16][65];
    __shared__ float Bs[16][65];
    int b = blockIdx.z;
    const float* A = d_HG + (size_t)b*N1*Dm;
    int tid = threadIdx.x;
    int tr = tid >> 4, tc = tid & 15;
    int r0 = blockIdx.y*64, c0 = blockIdx.x*64;
    float acc[4][4] = {};
    for (int k0 = 0; k0 < Dm; k0 += 16) {
        #pragma unroll
        for (int i = 0; i < 4; i++) {
            int e = tid + i*256;
            int rr = e >> 4, cc = e & 15;
            As[cc][rr] = A[(size_t)(r0+rr)*Dm + k0 + cc];
            Bs[cc][rr] = A[(size_t)(c0+rr)*Dm + k0 + cc];
        }
        __syncthreads();
        #pragma unroll
        for (int k = 0; k < 16; k++) {
            float a[4], bv[4];
            #pragma unroll
            for (int i = 0; i < 4; i++) a[i]  = As[k][tr + i*16];
            #pragma unroll
            for (int j = 0; j < 4; j++) bv[j] = Bs[k][tc + j*16];
            #pragma unroll
            for (int i = 0; i < 4; i++)
                #pragma unroll
                for (int j = 0; j < 4; j++) acc[i][j] += a[i]*bv[j];
        }
        __syncthreads();
    }
    #pragma unroll
    for (int i = 0; i < 4; i++) {
        int r = r0 + tr + i*16;
        float sqr = d_SQ[b*Nn + r];
        #pragma unroll
        for (int j = 0; j < 4; j++) {
            int c = c0 + tc + j*16;
            float v = sqr + d_SQ[b*Nn + c] - 2.f*acc[i][j];
            if (r == c) v = CUDART_INF_F;
            d_D2[((size_t)b*Nn + r)*Nn + c] = v;
        }
    }
}

// ------------------------- exact top-10 kNN -> adjacency bits ----------------
__global__ void k_topk()
{
    int warp = (blockIdx.x*blockDim.x + threadIdx.x) >> 5;
    int lane = threadIdx.x & 31;
    if (warp >= Bsz*Nn) return;
    int b = warp >> 10, i = warp & 1023;
    const float* row = d_D2 + (size_t)warp*Nn;
    float vals[32];
    #pragma unroll
    for (int t = 0; t < 32; t++) vals[t] = row[t*32 + lane];
    unsigned used = 0u;
    unsigned* adjb = d_ADJ + (size_t)b*N1*AW;
    for (int r = 0; r < KNN; r++) {
        float bv = CUDART_INF_F; int bj = 1 << 30;
        #pragma unroll
        for (int t = 0; t < 32; t++) {
            if (!((used >> t) & 1u)) {
                float v = vals[t]; int j = t*32 + lane;
                if (v < bv || (v == bv && j < bj)) { bv = v; bj = j; }
            }
        }
        #pragma unroll
        for (int o = 16; o; o >>= 1) {
            float ov = __shfl_xor_sync(0xffffffffu, bv, o);
            int   oj = __shfl_xor_sync(0xffffffffu, bj, o);
            if (ov < bv || (ov == bv && oj < bj)) { bv = ov; bj = oj; }
        }
        if (lane == (bj & 31)) used |= 1u << (bj >> 5);
        if (lane == 0) {
            atomicOr(&adjb[i*AW + (bj >> 5)], 1u << (bj & 31));
            atomicOr(&adjb[bj*AW + (i >> 5)], 1u << (i & 31));
        }
    }
}

// ------------------------- generic SGEMM: C = A[M,K] * W[N,K]^T --------------
// flags: 1 = +bias[N], 2 = +res[M,N], 4 = relu
__global__ void k_gemm(const float* __restrict__ A, const float* __restrict__ Bm,
                       const float* __restrict__ bias, const float* __restrict__ res,
                       float* __restrict__ C, int M, int Nc, int K, int flags)
{
    __shared__ float As[16][65];
    __shared__ float Bs[16][65];
    int tid = threadIdx.x;
    int tr = tid >> 4, tc = tid & 15;
    int r0 = blockIdx.y*64, c0 = blockIdx.x*64;
    float acc[4][4] = {};
    for (int k0 = 0; k0 < K; k0 += 16) {
        #pragma unroll
        for (int i = 0; i < 4; i++) {
            int e = tid + i*256;
            int rr = e >> 4, cc = e & 15;
            int gr = r0 + rr;
            As[cc][rr] = (gr < M) ? A[(size_t)gr*K + k0 + cc] : 0.f;
            int gn = c0 + rr;
            Bs[cc][rr] = (gn < Nc) ? Bm[(size_t)gn*K + k0 + cc] : 0.f;
        }
        __syncthreads();
        #pragma unroll
        for (int k = 0; k < 16; k++) {
            float a[4], bv[4];
            #pragma unroll
            for (int i = 0; i < 4; i++) a[i]  = As[k][tr + i*16];
            #pragma unroll
            for (int j = 0; j < 4; j++) bv[j] = Bs[k][tc + j*16];
            #pragma unroll
            for (int i = 0; i < 4; i++)
                #pragma unroll
                for (int j = 0; j < 4; j++) acc[i][j] += a[i]*bv[j];
        }
        __syncthreads();
    }
    #pragma unroll
    for (int i = 0; i < 4; i++) {
        int r = r0 + tr + i*16;
        if (r >= M) continue;
        #pragma unroll
        for (int j = 0; j < 4; j++) {
            int c = c0 + tc + j*16;
            if (c >= Nc) continue;
            float v = acc[i][j];
            if (flags & 1) v += bias[c];
            if (flags & 2) v += res[(size_t)r*Nc + c];
            if (flags & 4) v = fmaxf(v, 0.f);
            C[(size_t)r*Nc + c] = v;
        }
    }
}

// ------------------------- qe = Q . emb per (head,bucket) --------------------
__global__ void k_qe(const float* __restrict__ emb)
{
    __shared__ float qs[Dm];
    int row = blockIdx.x;              // b*N1 + n
    int tid = threadIdx.x;
    if (tid < Dm) qs[tid] = d_Q[(size_t)row*Dm + tid];
    __syncthreads();
    int h = tid >> 5, kb = tid & 31;
    const float* e = emb + kb*Dm + h*Dk;
    const float* q = qs + h*Dk;
    float s = 0.f;
    #pragma unroll
    for (int dd = 0; dd < Dk; dd++) s += q[dd]*e[dd];
    d_QE[(size_t)row*(Hh*NBk) + h*NBk + kb] = s;
}

// ------------------------- sparse masked attention ---------------------------
__device__ __forceinline__ void attn_word(unsigned word, int base,
    const float q[16], float cqx, float cqy,
    const float (*Ks)[17], const float (*Vs)[17],
    const float* ckx, const float* cky, const float* qerow,
    float& mrun, float& lrun, float acc[16])
{
    while (word) {
        int mm = base + (__ffs((int)word) - 1);
        word &= word - 1u;
        float s = 0.f;
        #pragma unroll
        for (int d = 0; d < 16; d++) s += q[d]*Ks[mm][d];
        float dx = cqx - ckx[mm], dy = cqy - cky[mm];
        float dist = sqrtf(dx*dx + dy*dy);
        int bk = (int)(dist * 32.f); if (bk > 31) bk = 31;
        s = s*SCALEf + qerow[bk];
        if (s > mrun) {
            float cr = __expf(mrun - s);        // first hit: exp(-inf)=0
            lrun = lrun*cr + 1.f;
            #pragma unroll
            for (int d = 0; d < 16; d++) acc[d] = acc[d]*cr + Vs[mm][d];
            mrun = s;
        } else {
            float p = __expf(s - mrun);
            lrun += p;
            #pragma unroll
            for (int d = 0; d < 16; d++) acc[d] += p*Vs[mm][d];
        }
    }
}

__global__ void k_attn(const float* __restrict__ coords)
{
    __shared__ float Ks[128][17];
    __shared__ float Vs[128][17];
    __shared__ float ckx[128], cky[128];
    __shared__ float qes[128][33];
    int b = blockIdx.z, h = blockIdx.y;
    int q0 = blockIdx.x * 128;
    int tid = threadIdx.x;
    int n = q0 + tid;
    bool qv = (n < N1);
    float q[16], acc[16];
    float cqx = 0.f, cqy = 0.f, mrun = -CUDART_INF_F, lrun = 0.f;
    #pragma unroll
    for (int d = 0; d < 16; d++) { q[d] = 0.f; acc[d] = 0.f; }
    const unsigned* rowadj = d_ADJ;
    if (qv) {
        const float* qp = d_Q + ((size_t)(b*N1 + n))*Dm + h*Dk;
        #pragma unroll
        for (int d = 0; d < 16; d++) q[d] = qp[d];
        if (n < Nn) { cqx = coords[(b*Nn+n)*2]; cqy = coords[(b*Nn+n)*2+1]; }
        const float* qep = d_QE + ((size_t)(b*N1 + n))*(Hh*NBk) + h*NBk;
        #pragma unroll
        for (int kb = 0; kb < 32; kb++) qes[tid][kb] = qep[kb];
        rowadj = d_ADJ + (size_t)(b*N1 + n)*AW;
    }
    for (int kt = 0; kt < 9; kt++) {
        int m0 = kt*128;
        int tlen = N1 - m0; if (tlen > 128) tlen = 128;
        __syncthreads();
        if (tid < tlen) {
            int m = m0 + tid;
            const float* kp = d_Kb + ((size_t)(b*N1 + m))*Dm + h*Dk;
            const float* vp = d_Vb + ((size_t)(b*N1 + m))*Dm + h*Dk;
            #pragma unroll
            for (int d = 0; d < 16; d++) { Ks[tid][d] = kp[d]; Vs[tid][d] = vp[d]; }
            if (m < Nn) { ckx[tid] = coords[(b*Nn+m)*2]; cky[tid] = coords[(b*Nn+m)*2+1]; }
            else        { ckx[tid] = 0.f; cky[tid] = 0.f; }
        }
        __syncthreads();
        if (!qv) continue;
        int wb = m0 >> 5;
        unsigned w0 = rowadj[wb];
        unsigned w1 = (wb+1 < AW) ? rowadj[wb+1] : 0u;
        unsigned w2 = (wb+2 < AW) ? rowadj[wb+2] : 0u;
        unsigned w3 = (wb+3 < AW) ? rowadj[wb+3] : 0u;
        attn_word(w0,  0, q, cqx, cqy, Ks, Vs, ckx, cky, qes[tid], mrun, lrun, acc);
        attn_word(w1, 32, q, cqx, cqy, Ks, Vs, ckx, cky, qes[tid], mrun, lrun, acc);
        attn_word(w2, 64, q, cqx, cqy, Ks, Vs, ckx, cky, qes[tid], mrun, lrun, acc);
        attn_word(w3, 96, q, cqx, cqy, Ks, Vs, ckx, cky, qes[tid], mrun, lrun, acc);
    }
    if (qv) {
        float inv = 1.f / lrun;
        float* o = d_CTX + ((size_t)(b*N1 + n))*Dm + h*Dk;
        #pragma unroll
        for (int d = 0; d < 16; d++) o[d] = acc[d]*inv;
    }
}

// ------------------------- instance norm over sequence axis ------------------
__global__ void k_inorm(const float* __restrict__ src, float* __restrict__ dst,
                        const float* __restrict__ w, const float* __restrict__ bb)
{
    __shared__ float red[8][Dm];
    __shared__ float s_mu[Dm], s_sc[Dm];
    int b = blockIdx.x;
    int d = threadIdx.x & 127;
    int g = threadIdx.x >> 7;
    const float* p = src + (size_t)b*N1*Dm;
    float s = 0.f;
    for (int n = g; n < N1; n += 8) s += p[n*Dm + d];
    red[g][d] = s;
    __syncthreads();
    if (g == 0) {
        float t = 0.f;
        #pragma unroll
        for (int i = 0; i < 8; i++) t += red[i][d];
        s_mu[d] = t * (1.f/N1);
    }
    __syncthreads();
    float mu = s_mu[d];
    float v = 0.f;
    for (int n = g; n < N1; n += 8) { float x = p[n*Dm + d] - mu; v += x*x; }
    __syncthreads();
    red[g][d] = v;
    __syncthreads();
    if (g == 0) {
        float t = 0.f;
        #pragma unroll
        for (int i = 0; i < 8; i++) t += red[i][d];
        s_sc[d] = rsqrtf(t*(1.f/N1) + EPSf) * w[d];
    }
    __syncthreads();
    float sc = s_sc[d], sh = bb[d];
    float* o = dst + (size_t)b*N1*Dm;
    for (int n = g; n < N1; n += 8) o[n*Dm + d] = (p[n*Dm + d] - mu)*sc + sh;
}

// ------------------------- final prep: X = h + p_multi; write p_multi --------
__global__ void k_final(float* __restrict__ out)
{
    int gid = blockIdx.x*blockDim.x + threadIdx.x;
    if (gid < Bsz*Dm) out[Bsz*Nn*Dm + gid] = d_POOL[gid] * (1.f/3.f);
    if (gid >= Bsz*Nn*Dm) return;
    int d = gid & 127;
    int n = (gid >> 7) & 1023;
    int b = gid >> 17;
    d_X[gid] = d_HG[((size_t)b*N1 + n)*Dm + d] + d_POOL[b*Dm + d]*(1.f/3.f);
}

// ------------------------- host driver ---------------------------------------
extern "C" void kernel_launch(void* const* d_in, const int* in_sizes, int n_in,
                              void* d_out, int out_size)
{
    const float* coords = (const float*)d_in[0];
    const float* in_W   = (const float*)d_in[1];
    const float* in_b   = (const float*)d_in[2];
    const float* gnode  = (const float*)d_in[3];
    const float* Wq     = (const float*)d_in[4];
    const float* Wk     = (const float*)d_in[5];
    const float* Wv     = (const float*)d_in[6];
    const float* Wo     = (const float*)d_in[7];
    const float* emb    = (const float*)d_in[8];
    const float* W1     = (const float*)d_in[9];
    const float* b1     = (const float*)d_in[10];
    const float* W2     = (const float*)d_in[11];
    const float* b2     = (const float*)d_in[12];
    const float* n1w    = (const float*)d_in[13];
    const float* n1b    = (const float*)d_in[14];
    const float* n2w    = (const float*)d_in[15];
    const float* n2b    = (const float*)d_in[16];
    const float* outW   = (const float*)d_in[17];
    const float* outb   = (const float*)d_in[18];
    float* out = (float*)d_out;

    float *HG, *Q, *Kb, *Vb, *CTX, *Y, *T1, *T2, *X;
    cudaGetSymbolAddress((void**)&HG,  d_HG);
    cudaGetSymbolAddress((void**)&Q,   d_Q);
    cudaGetSymbolAddress((void**)&Kb,  d_Kb);
    cudaGetSymbolAddress((void**)&Vb,  d_Vb);
    cudaGetSymbolAddress((void**)&CTX, d_CTX);
    cudaGetSymbolAddress((void**)&Y,   d_Y);
    cudaGetSymbolAddress((void**)&T1,  d_T1);
    cudaGetSymbolAddress((void**)&T2,  d_T2);
    cudaGetSymbolAddress((void**)&X,   d_X);

    const int Mall = Bsz*N1;  // 2050

    k_input<<<(Bsz*N1*Dm + 255)/256, 256>>>(coords, in_W, in_b, gnode);

    for (int l = 0; l < 3; l++) {
        k_colmean<<<Bsz, 1024>>>(1);                       // g += mean(h)
        k_init_adj<<<Bsz*N1, 64>>>();
        k_sqnorm<<<(Bsz*Nn*32 + 255)/256, 256>>>();
        { dim3 g(Nn/64, Nn/64, Bsz); k_d2<<<g, 256>>>(); }
        k_topk<<<(Bsz*Nn)/8, 256>>>();

        dim3 gq(Dm/64, (Mall + 63)/64);
        k_gemm<<<gq, 256>>>(HG, Wq + (size_t)l*Dm*Dm, nullptr, nullptr, Q,  Mall, Dm, Dm, 0);
        k_gemm<<<gq, 256>>>(HG, Wk + (size_t)l*Dm*Dm, nullptr, nullptr, Kb, Mall, Dm, Dm, 0);
        k_gemm<<<gq, 256>>>(HG, Wv + (size_t)l*Dm*Dm, nullptr, nullptr, Vb, Mall, Dm, Dm, 0);
        k_qe<<<Mall, 256>>>(emb + (size_t)l*NBk*Dm);
        { dim3 ga(9, Hh, Bsz); k_attn<<<ga, 128>>>(coords); }

        k_gemm<<<gq, 256>>>(CTX, Wo + (size_t)l*Dm*Dm, nullptr, HG, Y, Mall, Dm, Dm, 2);
        k_inorm<<<Bsz, 1024>>>(Y, Y, n1w + l*Dm, n1b + l*Dm);

        dim3 g1(Dff/64, (Mall + 63)/64);
        k_gemm<<<g1, 256>>>(Y,  W1 + (size_t)l*Dff*Dm, b1 + l*Dff, nullptr, T1, Mall, Dff, Dm, 1|4);
        k_gemm<<<gq, 256>>>(T1, W2 + (size_t)l*Dm*Dff, b2 + l*Dm,  Y,      T2, Mall, Dm, Dff, 1|2);
        k_inorm<<<Bsz, 1024>>>(T2, HG, n2w + l*Dm, n2b + l*Dm);

        k_colmean<<<Bsz, 1024>>>(2);                       // pool += mean(h)
    }

    k_final<<<(Bsz*Nn*Dm + 255)/256, 256>>>(out);
    { dim3 ge(Dm/64, (Bsz*Nn + 63)/64);
      k_gemm<<<ge, 256>>>(X, outW, outb, nullptr, out, Bsz*Nn, Dm, Dm, 1); }
}